// round 1
// baseline (speedup 1.0000x reference)
#include <cuda_runtime.h>
#include <cuda_bf16.h>
#include <math_constants.h>

#define D        32000
#define NROWS    4096
#define CAP      4096          // per-row candidate capacity in global scratch
#define TA       512           // threads, filter kernel
#define TB       256           // threads, bisect kernel (8 warps -> 8 rows)
#define REGCAP   1024          // candidates held in registers per warp (32 lanes * 32 regs)

// ---- device scratch (no allocations allowed) ----
__device__ float g_cand[(size_t)NROWS * CAP];   // 64 MB
__device__ float g_rowmax[NROWS];
__device__ int   g_count[NROWS];
__device__ float g_xt[NROWS];                   // X[row][target[row]]
__device__ float g_loss[NROWS];

// (1/32000)^(alpha-1) = 1/sqrt(32000), folded through double like the reference
#define CHI ((float)0.005590169943749474)

// ============================================================================
// Kernel A: per-row max + candidate compaction (deterministic)
// ============================================================================
extern __shared__ float s_row[];   // D floats

__global__ void __launch_bounds__(TA) filter_kernel(const float* __restrict__ X,
                                                    const int*   __restrict__ target)
{
    const int row  = blockIdx.x;
    const int tid  = threadIdx.x;
    const int lane = tid & 31;
    const int wid  = tid >> 5;
    const int NW   = TA / 32;

    const float4* Xr4 = reinterpret_cast<const float4*>(X + (size_t)row * D);
    float4* s4 = reinterpret_cast<float4*>(s_row);

    // load row, scale by (alpha-1)=0.5, stage in smem, track max
    float lmax = -CUDART_INF_F;
    for (int i = tid; i < D / 4; i += TA) {
        float4 v = Xr4[i];
        v.x *= 0.5f; v.y *= 0.5f; v.z *= 0.5f; v.w *= 0.5f;
        s4[i] = v;
        lmax = fmaxf(lmax, fmaxf(fmaxf(v.x, v.y), fmaxf(v.z, v.w)));
    }

    __shared__ float s_red[32];
    __shared__ int   s_wcnt[NW];
    __shared__ int   s_woff[NW + 1];

    #pragma unroll
    for (int o = 16; o; o >>= 1) lmax = fmaxf(lmax, __shfl_xor_sync(0xffffffffu, lmax, o));
    if (lane == 0) s_red[wid] = lmax;
    __syncthreads();
    if (tid < 32) {
        float v = (tid < NW) ? s_red[tid] : -CUDART_INF_F;
        #pragma unroll
        for (int o = 16; o; o >>= 1) v = fmaxf(v, __shfl_xor_sync(0xffffffffu, v, o));
        if (tid == 0) s_red[0] = v;
    }
    __syncthreads();
    const float rmax   = s_red[0];
    const float thresh = rmax - 1.0f;   // tau_lo0; elements <= this contribute 0 everywhere

    // pass 1: per-warp candidate counts (uniform trip count for ballot)
    const int iters = (D + TA - 1) / TA;
    int wcnt = 0;
    for (int k = 0; k < iters; k++) {
        int i = tid + k * TA;
        bool pred = (i < D) && (s_row[i] > thresh);
        unsigned m = __ballot_sync(0xffffffffu, pred);
        wcnt += __popc(m);
    }
    if (lane == 0) s_wcnt[wid] = wcnt;
    __syncthreads();
    if (tid == 0) {
        int acc = 0;
        for (int w = 0; w < NW; w++) { s_woff[w] = acc; acc += s_wcnt[w]; }
        s_woff[NW] = acc;
    }
    __syncthreads();

    // pass 2: deterministic compaction
    float* out = g_cand + (size_t)row * CAP;
    int off = s_woff[wid];
    for (int k = 0; k < iters; k++) {
        int i = tid + k * TA;
        bool pred = (i < D) && (s_row[i] > thresh);
        unsigned m = __ballot_sync(0xffffffffu, pred);
        if (pred) {
            int pos = off + __popc(m & ((1u << lane) - 1u));
            if (pos < CAP) out[pos] = s_row[i];
        }
        off += __popc(m);
    }

    if (tid == 0) {
        g_count[row]  = s_woff[NW];
        g_rowmax[row] = rmax;
        int t = target[row];
        g_xt[row] = 2.0f * s_row[t];   // exact: 2*(0.5*x) == x in fp32
    }
}

// ============================================================================
// Kernel B: one warp per row — 50 bisection iterations, warp-synchronous
// ============================================================================
__device__ __forceinline__ float warp_sum(float v) {
    #pragma unroll
    for (int o = 16; o; o >>= 1) v += __shfl_xor_sync(0xffffffffu, v, o);
    return v;
}

__global__ void __launch_bounds__(TB) bisect_kernel(const float* __restrict__ X)
{
    const int gw = blockIdx.x * (TB / 32) + (threadIdx.x >> 5);
    if (gw >= NROWS) return;
    const int lane = threadIdx.x & 31;
    const int row  = gw;

    const int   count = g_count[row];
    const float rmax  = g_rowmax[row];
    const float* cand = g_cand + (size_t)row * CAP;
    const float* Xr   = X + (size_t)row * D;

    const bool big  = (count > CAP);               // pathological: stream full row
    const bool tail = (!big) && (count > REGCAP);  // extra candidates from L2
    const int  cnt_reg = big ? 0 : min(count, REGCAP);

    float c[32];
    #pragma unroll
    for (int r = 0; r < 32; r++) {
        int i = lane + 32 * r;
        c[r] = (i < cnt_reg) ? cand[i] : -1e30f;   // pad -> contributes exactly 0
    }

    float tau_lo = rmax - 1.0f;
    const float tau_hi = rmax - CHI;

    auto feval = [&](float tau) -> float {
        float acc = 0.f;
        #pragma unroll
        for (int r = 0; r < 32; r++) {
            float t = fmaxf(c[r] - tau, 0.f);
            acc = fmaf(t, t, acc);
        }
        if (tail) {
            for (int i = REGCAP + lane; i < count; i += 32) {
                float t = fmaxf(cand[i] - tau, 0.f);
                acc = fmaf(t, t, acc);
            }
        }
        if (big) {
            for (int i = lane; i < D; i += 32) {
                float t = fmaxf(0.5f * Xr[i] - tau, 0.f);
                acc = fmaf(t, t, acc);
            }
        }
        return warp_sum(acc);
    };

    const float f_lo = feval(tau_lo) - 1.0f;   // computed ONCE (matches reference closure)
    float dm = tau_hi - tau_lo;
    float tau_m = tau_lo;
    #pragma unroll 1
    for (int it = 0; it < 50; it++) {
        dm *= 0.5f;
        tau_m = tau_lo + dm;
        float f_m = feval(tau_m) - 1.0f;
        if (f_m * f_lo >= 0.f) tau_lo = tau_m;
    }

    // final: p_raw = max(Xa - tau_m, 0)^2 ; S = sum p_raw
    // sum p^1.5 = (sum t^3) / S^1.5 ; sum p*X = 2 * (sum p_raw * Xa) / S
    float S = 0.f, A15 = 0.f, PX = 0.f;
    #pragma unroll
    for (int r = 0; r < 32; r++) {
        float t  = fmaxf(c[r] - tau_m, 0.f);
        float pr = t * t;
        S   += pr;
        A15  = fmaf(pr, t,    A15);
        PX   = fmaf(pr, c[r], PX);
    }
    if (tail) {
        for (int i = REGCAP + lane; i < count; i += 32) {
            float v = cand[i];
            float t = fmaxf(v - tau_m, 0.f);
            float pr = t * t;
            S += pr; A15 = fmaf(pr, t, A15); PX = fmaf(pr, v, PX);
        }
    }
    if (big) {
        for (int i = lane; i < D; i += 32) {
            float v = 0.5f * Xr[i];
            float t = fmaxf(v - tau_m, 0.f);
            float pr = t * t;
            S += pr; A15 = fmaf(pr, t, A15); PX = fmaf(pr, v, PX);
        }
    }
    S   = warp_sum(S);
    A15 = warp_sum(A15);
    PX  = warp_sum(PX);

    float sum_p15 = A15 / (S * sqrtf(S));
    float omega   = (1.0f - sum_p15) / 0.75f;     // alpha*(alpha-1) = 0.75
    float loss    = omega + 2.0f * PX / S - g_xt[row];

    if (lane == 0) g_loss[row] = loss;
}

// ============================================================================
// Kernel C: deterministic mean over rows
// ============================================================================
__global__ void __launch_bounds__(1024) reduce_kernel(float* __restrict__ out)
{
    __shared__ float s[1024];
    float a = 0.f;
    for (int i = threadIdx.x; i < NROWS; i += 1024) a += g_loss[i];
    s[threadIdx.x] = a;
    __syncthreads();
    #pragma unroll
    for (int o = 512; o; o >>= 1) {
        if (threadIdx.x < o) s[threadIdx.x] += s[threadIdx.x + o];
        __syncthreads();
    }
    if (threadIdx.x == 0) out[0] = s[0] / (float)NROWS;
}

// ============================================================================
extern "C" void kernel_launch(void* const* d_in, const int* in_sizes, int n_in,
                              void* d_out, int out_size)
{
    const float* X      = (const float*)d_in[0];
    const int*   target = (const int*)  d_in[1];
    float*       out    = (float*)d_out;

    const int smemA = D * (int)sizeof(float);  // 128000 B
    cudaFuncSetAttribute(filter_kernel, cudaFuncAttributeMaxDynamicSharedMemorySize, smemA);

    filter_kernel<<<NROWS, TA, smemA>>>(X, target);
    bisect_kernel<<<(NROWS * 32 + TB - 1) / TB, TB>>>(X);
    reduce_kernel<<<1, 1024>>>(out);
}